// round 2
// baseline (speedup 1.0000x reference)
#include <cuda_runtime.h>
#include <cstdint>
#include <cstddef>

#define BB   128            // batch
#define SEQ  720
#define PRED 336
#define ENC  321
#define DD   512
#define NG   2048           // 4*D
#define KC   833            // ENC + D
#define KPAD 864            // padded encoder K (9 * 96)
#define XSTR (SEQ*ENC)
#define NBLK 144            // persistent grid: 16 n-tiles x 9 k-splits (<= 148 SMs)
#define EPAD 384            // padded ENC for W_pred^T

// -------- persistent device scratch (no allocations allowed) --------
__device__ float g_WT [KPAD * NG];       // encoder: [Wih|Whh]^T gate-interleaved [k][n], n=d*4+gate
__device__ float g_WD [DD * NG];         // decoder: (Wih@Wp + Whh)^T gate-interleaved [k][n]
__device__ float g_WpT2[DD * EPAD];      // W_pred^T padded: [k][e], zeros for e>=321
__device__ float g_bias [NG];            // enc bias (b_ih + b_hh), interleaved
__device__ float g_biasd[NG];            // dec bias (b_ih + b_hh + Wih@b_pred), interleaved
__device__ float g_h[BB * DD];
__device__ float g_c[BB * DD];
__device__ float g_part[9 * BB * NG];    // split-K partials
__device__ float g_hist[(size_t)PRED * BB * DD];  // decoder h_t log (88 MB)

__device__ volatile unsigned g_bar_gen;
__device__ unsigned g_bar_cnt;

// -------- packed fp32x2 FMA (sm_100+) --------
__device__ __forceinline__ void fma2(float2 &d, float2 a, float2 b) {
    unsigned long long &du = reinterpret_cast<unsigned long long &>(d);
    unsigned long long au  = reinterpret_cast<unsigned long long &>(a);
    unsigned long long bu  = reinterpret_cast<unsigned long long &>(b);
    asm("fma.rn.f32x2 %0, %1, %2, %0;" : "+l"(du) : "l"(au), "l"(bu));
}

__device__ __forceinline__ float sigm(float x) { return 1.f / (1.f + __expf(-x)); }

// -------- software grid barrier (all NBLK blocks co-resident) --------
__device__ __forceinline__ void grid_sync() {
    __threadfence();
    __syncthreads();
    if (threadIdx.x == 0) {
        unsigned gen = g_bar_gen;
        if (atomicAdd(&g_bar_cnt, 1u) == NBLK - 1) {
            g_bar_cnt = 0;
            __threadfence();
            g_bar_gen = gen + 1;
        } else {
            while (g_bar_gen == gen) { __nanosleep(64); }
        }
        __threadfence();
    }
    __syncthreads();
}

// ==================== weight prep ====================
__global__ void prep_wt(const float *__restrict__ Wih, const float *__restrict__ Whh)
{
    int idx = blockIdx.x * 256 + threadIdx.x;
    if (idx >= KPAD * NG) return;
    int k = idx / NG, n = idx - k * NG;
    int d = n >> 2, gate = n & 3;
    int j = gate * DD + d;
    float v = 0.f;
    if (k < ENC)       v = Wih[j * ENC + k];
    else if (k < KC)   v = Whh[j * DD + (k - ENC)];
    g_WT[idx] = v;
}

__global__ void prep_wpt2(const float *__restrict__ Wp)
{
    int idx = blockIdx.x * 256 + threadIdx.x;   // 512*384
    if (idx >= DD * EPAD) return;
    int k = idx / EPAD, e = idx - k * EPAD;
    g_WpT2[idx] = (e < ENC) ? Wp[(size_t)e * DD + k] : 0.f;
}

// g_WD[k][n] = sum_e Wih[j][e] * Wp[e][k] + Whh[j][k],  j = gate*512+d, n = d*4+gate
__global__ void prep_wd(const float *__restrict__ Wih, const float *__restrict__ Whh)
{
    __shared__ float sW[EPAD];   // padded Wih row
    const int j = blockIdx.x;    // 0..2047
    const int tid = threadIdx.x; // 128 threads
    for (int e = tid; e < EPAD; e += 128) sW[e] = (e < ENC) ? Wih[(size_t)j * ENC + e] : 0.f;
    __syncthreads();
    const int d = j & 511, gate = j >> 9;
    const int n = d * 4 + gate;
    for (int k = tid; k < DD; k += 128) {
        float a0 = 0.f, a1 = 0.f, a2 = 0.f, a3 = 0.f;
        const float *wr = &g_WpT2[(size_t)k * EPAD];
        for (int e = 0; e < EPAD; e += 4) {
            const float4 wv = *(const float4 *)&wr[e];
            const float4 sv = *(const float4 *)&sW[e];
            a0 += sv.x * wv.x; a1 += sv.y * wv.y; a2 += sv.z * wv.z; a3 += sv.w * wv.w;
        }
        g_WD[(size_t)k * NG + n] = (a0 + a1) + (a2 + a3) + Whh[(size_t)j * DD + k];
    }
}

__global__ void prep_misc(const float *__restrict__ bih, const float *__restrict__ bhh,
                          const float *__restrict__ bp, const float *__restrict__ Wih)
{
    int idx = blockIdx.x * 256 + threadIdx.x;
    if (idx < NG) {                 // idx == j
        int j = idx;
        int n = (j & 511) * 4 + (j >> 9);
        float base = bih[j] + bhh[j];
        g_bias[n] = base;
        float acc = 0.f;
        const float *wr = &Wih[(size_t)j * ENC];
        for (int e = 0; e < ENC; ++e) acc += wr[e] * bp[e];
        g_biasd[n] = base + acc;
    }
    if (idx < BB * DD) { g_h[idx] = 0.f; g_c[idx] = 0.f; }
}

// ==================== persistent LSTM kernel ====================
// gate GEMM phase: split-K tile, BM=128, BN=128, BK=8, thread tile 8x8 (f32x2 packed)
template<int NCH, bool EPH>
__device__ __forceinline__ void gemm_phase(const float *__restrict__ xp, int xstride,
                                           const float *__restrict__ W,
                                           float *Us, float *Ws, int z, int nbase)
{
    const int tid = threadIdx.x;
    const int tm8 = (tid >> 4) * 8;
    const int tn8 = (tid & 15) * 8;

    float2 acc[8][4];
#pragma unroll
    for (int r = 0; r < 8; ++r)
#pragma unroll
        for (int c = 0; c < 4; ++c) acc[r][c] = make_float2(0.f, 0.f);

    int klp[4], mmp[4], kwp[4], nlp[4];
#pragma unroll
    for (int p = 0; p < 4; ++p) {
        int lin = tid + p * 256;
        klp[p] = lin & 7;   mmp[p] = lin >> 3;
        nlp[p] = lin & 127; kwp[p] = lin >> 7;
    }

    const int k0 = z * NCH * 8;
    float ur[4], wr[4];
    auto load_regs = [&](int kbase) {
#pragma unroll
        for (int p = 0; p < 4; ++p) {
            int k = kbase + klp[p];
            float v;
            if (EPH) {
                v = 0.f;
                if (k < ENC)     v = xp[(size_t)mmp[p] * xstride + k];
                else if (k < KC) v = __ldcg(&g_h[mmp[p] * DD + (k - ENC)]);
            } else {
                v = __ldcg(&g_h[mmp[p] * DD + k]);
            }
            ur[p] = v;
            wr[p] = W[(size_t)(kbase + kwp[p]) * NG + nbase + nlp[p]];
        }
    };

    load_regs(k0);
#pragma unroll 1
    for (int c8 = 0; c8 < NCH; ++c8) {
#pragma unroll
        for (int p = 0; p < 4; ++p) {
            Us[klp[p] * 132 + mmp[p]] = ur[p];
            Ws[kwp[p] * 128 + nlp[p]] = wr[p];
        }
        __syncthreads();
        if (c8 < NCH - 1) load_regs(k0 + (c8 + 1) * 8);
#pragma unroll
        for (int q = 0; q < 8; ++q) {
            const float4 a0 = *(const float4 *)&Us[q * 132 + tm8];
            const float4 a1 = *(const float4 *)&Us[q * 132 + tm8 + 4];
            const float4 b0 = *(const float4 *)&Ws[q * 128 + tn8];
            const float4 b1 = *(const float4 *)&Ws[q * 128 + tn8 + 4];
            float  av[8] = {a0.x, a0.y, a0.z, a0.w, a1.x, a1.y, a1.z, a1.w};
            float2 bv[4] = {make_float2(b0.x, b0.y), make_float2(b0.z, b0.w),
                            make_float2(b1.x, b1.y), make_float2(b1.z, b1.w)};
#pragma unroll
            for (int r = 0; r < 8; ++r) {
                float2 ad = make_float2(av[r], av[r]);
#pragma unroll
                for (int c = 0; c < 4; ++c) fma2(acc[r][c], ad, bv[c]);
            }
        }
        __syncthreads();
    }

#pragma unroll
    for (int r = 0; r < 8; ++r) {
        int m = tm8 + r;
        float *dst = &g_part[((size_t)z * BB + m) * NG + nbase + tn8];
        *(float4 *)dst       = make_float4(acc[r][0].x, acc[r][0].y, acc[r][1].x, acc[r][1].y);
        *(float4 *)(dst + 4) = make_float4(acc[r][2].x, acc[r][2].y, acc[r][3].x, acc[r][3].y);
    }
}

// reduce split-K partials + LSTM cell (deterministic order)
template<int NS>
__device__ __forceinline__ void update_phase(const float *__restrict__ bias, float *hist)
{
    int gtid = blockIdx.x * 256 + threadIdx.x;
    for (int id = gtid; id < BB * DD; id += NBLK * 256) {
        int b = id >> 9, d = id & 511;
        float4 g = make_float4(0.f, 0.f, 0.f, 0.f);
#pragma unroll
        for (int s = 0; s < NS; ++s) {
            const float4 v = __ldcg((const float4 *)&g_part[((size_t)s * BB + b) * NG + d * 4]);
            g.x += v.x; g.y += v.y; g.z += v.z; g.w += v.w;
        }
        const float4 bb = *(const float4 *)&bias[d * 4];
        float gi = g.x + bb.x, gf = g.y + bb.y, gg = g.z + bb.z, go = g.w + bb.w;
        float c  = g_c[id];
        float cn = sigm(gf) * c + sigm(gi) * tanhf(gg);
        float hn = sigm(go) * tanhf(cn);
        g_c[id] = cn;
        g_h[id] = hn;
        if (hist) hist[id] = hn;
    }
}

__global__ __launch_bounds__(256, 1) void lstm_persistent(const float *__restrict__ x)
{
    __shared__ float Us[8 * 132];
    __shared__ float Ws[8 * 128];
    const int bx    = blockIdx.x;
    const int z     = bx >> 4;          // 0..8
    const int nbase = (bx & 15) * 128;

    // encoder: 720 serial steps, K = 864 (9 splits x 96)
    for (int t = 0; t < SEQ; ++t) {
        gemm_phase<12, true>(x + (size_t)t * ENC, XSTR, g_WT, Us, Ws, z, nbase);
        grid_sync();
        update_phase<9>(g_bias, (t == SEQ - 1) ? g_hist : nullptr);
        grid_sync();
    }
    // decoder: gates = h @ (Wih@Wp + Whh)^T + bias_dec, K = 512 (8 splits x 64)
    for (int t = 0; t < PRED - 1; ++t) {
        if (z < 8) gemm_phase<8, false>(nullptr, 0, g_WD, Us, Ws, z, nbase);
        grid_sync();
        update_phase<8>(g_biasd, g_hist + (size_t)(t + 1) * BB * DD);
        grid_sync();
    }
}

// ==================== batched output projection ====================
// out[b][t][e] = g_hist[t][b][:] . W_pred[e][:] + b_pred[e]
__global__ __launch_bounds__(256) void final_pred(const float *__restrict__ bp,
                                                  float *__restrict__ out)
{
    __shared__ float As[8 * 132];
    __shared__ float Bs[8 * 128];
    const int t     = blockIdx.y;
    const int ebase = blockIdx.x * 128;
    const float *A  = g_hist + (size_t)t * BB * DD;

    const int tid = threadIdx.x;
    const int tm8 = (tid >> 4) * 8;
    const int tn8 = (tid & 15) * 8;

    float2 acc[8][4];
#pragma unroll
    for (int r = 0; r < 8; ++r)
#pragma unroll
        for (int c = 0; c < 4; ++c) acc[r][c] = make_float2(0.f, 0.f);

    int klp[4], mmp[4], kwp[4], nlp[4];
#pragma unroll
    for (int p = 0; p < 4; ++p) {
        int lin = tid + p * 256;
        klp[p] = lin & 7;   mmp[p] = lin >> 3;
        nlp[p] = lin & 127; kwp[p] = lin >> 7;
    }

    float ar[4], br[4];
    auto load_regs = [&](int kbase) {
#pragma unroll
        for (int p = 0; p < 4; ++p) {
            ar[p] = A[(size_t)mmp[p] * DD + kbase + klp[p]];
            br[p] = g_WpT2[(size_t)(kbase + kwp[p]) * EPAD + ebase + nlp[p]];
        }
    };

    load_regs(0);
#pragma unroll 1
    for (int c8 = 0; c8 < 64; ++c8) {
#pragma unroll
        for (int p = 0; p < 4; ++p) {
            As[klp[p] * 132 + mmp[p]] = ar[p];
            Bs[kwp[p] * 128 + nlp[p]] = br[p];
        }
        __syncthreads();
        if (c8 < 63) load_regs((c8 + 1) * 8);
#pragma unroll
        for (int q = 0; q < 8; ++q) {
            const float4 a0 = *(const float4 *)&As[q * 132 + tm8];
            const float4 a1 = *(const float4 *)&As[q * 132 + tm8 + 4];
            const float4 b0 = *(const float4 *)&Bs[q * 128 + tn8];
            const float4 b1 = *(const float4 *)&Bs[q * 128 + tn8 + 4];
            float  av[8] = {a0.x, a0.y, a0.z, a0.w, a1.x, a1.y, a1.z, a1.w};
            float2 bv[4] = {make_float2(b0.x, b0.y), make_float2(b0.z, b0.w),
                            make_float2(b1.x, b1.y), make_float2(b1.z, b1.w)};
#pragma unroll
            for (int r = 0; r < 8; ++r) {
                float2 ad = make_float2(av[r], av[r]);
#pragma unroll
                for (int c = 0; c < 4; ++c) fma2(acc[r][c], ad, bv[c]);
            }
        }
        __syncthreads();
    }

#pragma unroll
    for (int r = 0; r < 8; ++r) {
        int b = tm8 + r;
        float *orow = out + ((size_t)b * PRED + t) * ENC;
        float vals[8] = {acc[r][0].x, acc[r][0].y, acc[r][1].x, acc[r][1].y,
                         acc[r][2].x, acc[r][2].y, acc[r][3].x, acc[r][3].y};
#pragma unroll
        for (int c = 0; c < 8; ++c) {
            int e = ebase + tn8 + c;
            if (e < ENC) orow[e] = vals[c] + bp[e];
        }
    }
}

extern "C" void kernel_launch(void *const *d_in, const int *in_sizes, int n_in,
                              void *d_out, int out_size)
{
    const float *x   = (const float *)d_in[0];
    const float *Wih = (const float *)d_in[1];
    const float *Whh = (const float *)d_in[2];
    const float *bih = (const float *)d_in[3];
    const float *bhh = (const float *)d_in[4];
    const float *Wp  = (const float *)d_in[5];
    const float *bp  = (const float *)d_in[6];
    float *out = (float *)d_out;

    prep_wt  <<<(KPAD * NG + 255) / 256, 256>>>(Wih, Whh);
    prep_wpt2<<<(DD * EPAD + 255) / 256, 256>>>(Wp);
    prep_wd  <<<NG, 128>>>(Wih, Whh);
    prep_misc<<<(BB * DD + 255) / 256, 256>>>(bih, bhh, bp, Wih);

    lstm_persistent<<<NBLK, 256>>>(x);
    final_pred<<<dim3(3, PRED), 256>>>(bp, out);
}

// round 5
// speedup vs baseline: 1.0160x; 1.0160x over previous
#include <cuda_runtime.h>
#include <cstdint>
#include <cstddef>

#define BB   128
#define SEQ  720
#define PRED 336
#define ENC  321
#define DD   512
#define NG   2048           // 4*D
#define XSTR (SEQ*ENC)
#define KXP  328            // ENC padded to 41*8
#define EPAD 384            // ENC padded for W_pred^T tiles
#define NBLK 128            // persistent grid: 16 n-tiles x 8 k-splits

// -------- persistent device scratch (static, no runtime allocation) --------
__device__ float g_WX  [KXP * NG];        // Wih^T gate-interleaved [k][n], n=d*4+gate
__device__ float g_WE  [DD * NG];         // Whh^T gate-interleaved
__device__ float g_WD  [DD * NG];         // decoder (Wih@Wp + Whh)^T gate-interleaved
__device__ float g_WpT2[DD * EPAD];       // W_pred^T padded [k][e]
__device__ float g_bias [NG];
__device__ float g_biasd[NG];
__device__ float g_h[BB * DD];
__device__ float g_c[BB * DD];
__device__ float g_part[8 * BB * NG];                 // split-K partials
__device__ float g_xg[(size_t)SEQ * BB * NG];         // precomputed x projections (755 MB)
__device__ float g_hist[(size_t)PRED * BB * DD];      // decoder h_t log

__device__ volatile unsigned g_bar_gen;
__device__ unsigned g_bar_cnt;

// -------- packed fp32x2 FMA --------
__device__ __forceinline__ void fma2(float2 &d, float2 a, float2 b) {
    unsigned long long &du = reinterpret_cast<unsigned long long &>(d);
    unsigned long long au  = reinterpret_cast<unsigned long long &>(a);
    unsigned long long bu  = reinterpret_cast<unsigned long long &>(b);
    asm("fma.rn.f32x2 %0, %1, %2, %0;" : "+l"(du) : "l"(au), "l"(bu));
}

__device__ __forceinline__ float sigm(float x) { return 1.f / (1.f + __expf(-x)); }

// -------- grid barrier --------
__device__ __forceinline__ void grid_sync() {
    __syncthreads();
    if (threadIdx.x == 0) {
        __threadfence();
        unsigned gen = g_bar_gen;
        if (atomicAdd(&g_bar_cnt, 1u) == NBLK - 1) {
            g_bar_cnt = 0;
            __threadfence();
            g_bar_gen = gen + 1;
        } else {
            int sp = 0;
            while (g_bar_gen == gen) { if (++sp > 100) __nanosleep(40); }
        }
        __threadfence();
    }
    __syncthreads();
}

// -------- shared GEMM micro-kernel pieces --------
struct Slots { int klp[4], mmp[4], kwp[4], nlp[4]; };

__device__ __forceinline__ void make_slots(Slots &s, int tid) {
#pragma unroll
    for (int p = 0; p < 4; ++p) {
        int lin = tid + p * 256;
        s.klp[p] = lin & 7;   s.mmp[p] = lin >> 3;
        s.nlp[p] = lin & 127; s.kwp[p] = lin >> 7;
    }
}

__device__ __forceinline__ void stage(const Slots &s, const float *ur, const float *wr,
                                      float *U, float *W) {
#pragma unroll
    for (int p = 0; p < 4; ++p) {
        U[s.klp[p] * 132 + s.mmp[p]] = ur[p];
        W[s.kwp[p] * 128 + s.nlp[p]] = wr[p];
    }
}

__device__ __forceinline__ void mma8(float2 acc[8][4], const float *U, const float *W,
                                     int tm8, int tn8) {
#pragma unroll
    for (int q = 0; q < 8; ++q) {
        const float4 a0 = *(const float4 *)&U[q * 132 + tm8];
        const float4 a1 = *(const float4 *)&U[q * 132 + tm8 + 4];
        const float4 b0 = *(const float4 *)&W[q * 128 + tn8];
        const float4 b1 = *(const float4 *)&W[q * 128 + tn8 + 4];
        float  av[8] = {a0.x, a0.y, a0.z, a0.w, a1.x, a1.y, a1.z, a1.w};
        float2 bv[4] = {make_float2(b0.x, b0.y), make_float2(b0.z, b0.w),
                        make_float2(b1.x, b1.y), make_float2(b1.z, b1.w)};
#pragma unroll
        for (int r = 0; r < 8; ++r) {
            float2 ad = make_float2(av[r], av[r]);
#pragma unroll
            for (int c = 0; c < 4; ++c) fma2(acc[r][c], ad, bv[c]);
        }
    }
}

// ==================== prep kernels ====================
__global__ void prepA(const float *__restrict__ Wih, const float *__restrict__ Whh,
                      const float *__restrict__ bih, const float *__restrict__ bhh,
                      const float *__restrict__ Wp)
{
    int idx = blockIdx.x * 256 + threadIdx.x;
    if (idx < KXP * NG) {
        int k = idx / NG, n = idx - k * NG, d = n >> 2, gate = n & 3, j = gate * DD + d;
        g_WX[idx] = (k < ENC) ? Wih[(size_t)j * ENC + k] : 0.f;
    }
    if (idx < DD * NG) {
        int k = idx / NG, n = idx - k * NG, d = n >> 2, gate = n & 3, j = gate * DD + d;
        g_WE[idx] = Whh[(size_t)j * DD + k];
    }
    if (idx < DD * EPAD) {
        int k = idx / EPAD, e = idx - k * EPAD;
        g_WpT2[idx] = (e < ENC) ? Wp[(size_t)e * DD + k] : 0.f;
    }
    if (idx < NG) {
        int j = idx, n = (j & 511) * 4 + (j >> 9);
        g_bias[n] = bih[j] + bhh[j];
    }
    if (idx < BB * DD) { g_h[idx] = 0.f; g_c[idx] = 0.f; }
}

// g_WD[k][n] = sum_e Wih[j][e]*Wp[e][k] + Whh[j][k];  biasd[n] = bias[n] + Wih[j]·bp
__global__ void prepB(const float *__restrict__ Wih, const float *__restrict__ Whh,
                      const float *__restrict__ bp)
{
    __shared__ float sW[EPAD];
    __shared__ float red[128];
    const int j = blockIdx.x, tid = threadIdx.x;
    for (int e = tid; e < EPAD; e += 128) sW[e] = (e < ENC) ? Wih[(size_t)j * ENC + e] : 0.f;
    __syncthreads();
    const int d = j & 511, gate = j >> 9, n = d * 4 + gate;
    for (int k = tid; k < DD; k += 128) {
        float a0 = 0.f, a1 = 0.f, a2 = 0.f, a3 = 0.f;
        const float *wr = &g_WpT2[(size_t)k * EPAD];
        for (int e = 0; e < EPAD; e += 4) {
            const float4 wv = *(const float4 *)&wr[e];
            const float4 sv = *(const float4 *)&sW[e];
            a0 += sv.x * wv.x; a1 += sv.y * wv.y; a2 += sv.z * wv.z; a3 += sv.w * wv.w;
        }
        g_WD[(size_t)k * NG + n] = (a0 + a1) + (a2 + a3) + Whh[(size_t)j * DD + k];
    }
    float p = 0.f;
    for (int e = tid; e < ENC; e += 128) p += sW[e] * bp[e];
    red[tid] = p; __syncthreads();
    for (int off = 64; off; off >>= 1) { if (tid < off) red[tid] += red[tid + off]; __syncthreads(); }
    if (tid == 0) g_biasd[n] = g_bias[n] + red[0];
}

// ==================== parallel input projection: xg[t][b][n] ====================
// grid (16, 720), block 256. K = 321 (padded 328), no split-K.
__global__ __launch_bounds__(256) void xg_proj(const float *__restrict__ x)
{
    __shared__ float Us[2][8 * 132];
    __shared__ float Ws[2][8 * 128];
    const int t = blockIdx.y, nbase = blockIdx.x * 128, tid = threadIdx.x;
    const int tm8 = (tid >> 4) * 8, tn8 = (tid & 15) * 8;
    const float *xbase = x + (size_t)t * ENC;

    Slots s; make_slots(s, tid);
    float2 acc[8][4];
#pragma unroll
    for (int r = 0; r < 8; ++r)
#pragma unroll
        for (int c = 0; c < 4; ++c) acc[r][c] = make_float2(0.f, 0.f);

    float ur[4], wr[4];
    auto load = [&](int kb) {
#pragma unroll
        for (int p = 0; p < 4; ++p) {
            int k = kb + s.klp[p];
            ur[p] = (k < ENC) ? __ldg(&xbase[(size_t)s.mmp[p] * XSTR + k]) : 0.f;
            wr[p] = g_WX[(size_t)(kb + s.kwp[p]) * NG + nbase + s.nlp[p]];
        }
    };

    int buf = 0;
    load(0);
    stage(s, ur, wr, Us[0], Ws[0]);
    __syncthreads();
#pragma unroll 1
    for (int c8 = 0; c8 < 41; ++c8) {
        if (c8 < 40) load((c8 + 1) * 8);
        mma8(acc, Us[buf], Ws[buf], tm8, tn8);
        if (c8 < 40) { stage(s, ur, wr, Us[buf ^ 1], Ws[buf ^ 1]); __syncthreads(); buf ^= 1; }
    }
#pragma unroll
    for (int r = 0; r < 8; ++r) {
        float *dst = &g_xg[((size_t)t * BB + tm8 + r) * NG + nbase + tn8];
        *(float4 *)dst       = make_float4(acc[r][0].x, acc[r][0].y, acc[r][1].x, acc[r][1].y);
        *(float4 *)(dst + 4) = make_float4(acc[r][2].x, acc[r][2].y, acc[r][3].x, acc[r][3].y);
    }
}

// ==================== persistent recurrent kernel ====================
__device__ __forceinline__ void gemm_rec(const float *__restrict__ W,
                                         float Us[2][8 * 132], float Ws[2][8 * 128],
                                         int z, int nbase, const Slots &s, int tid)
{
    const int tm8 = (tid >> 4) * 8, tn8 = (tid & 15) * 8;
    float2 acc[8][4];
#pragma unroll
    for (int r = 0; r < 8; ++r)
#pragma unroll
        for (int c = 0; c < 4; ++c) acc[r][c] = make_float2(0.f, 0.f);

    const int k0 = z * 64;
    float ur[4], wr[4];
    auto load = [&](int kb) {
#pragma unroll
        for (int p = 0; p < 4; ++p) {
            ur[p] = __ldcg(&g_h[s.mmp[p] * DD + kb + s.klp[p]]);
            wr[p] = W[(size_t)(kb + s.kwp[p]) * NG + nbase + s.nlp[p]];
        }
    };

    int buf = 0;
    load(k0);
    stage(s, ur, wr, Us[0], Ws[0]);
    __syncthreads();
#pragma unroll 1
    for (int c8 = 0; c8 < 8; ++c8) {
        if (c8 < 7) load(k0 + (c8 + 1) * 8);
        mma8(acc, Us[buf], Ws[buf], tm8, tn8);
        if (c8 < 7) { stage(s, ur, wr, Us[buf ^ 1], Ws[buf ^ 1]); __syncthreads(); buf ^= 1; }
    }
#pragma unroll
    for (int r = 0; r < 8; ++r) {
        float *dst = &g_part[((size_t)z * BB + tm8 + r) * NG + nbase + tn8];
        *(float4 *)dst       = make_float4(acc[r][0].x, acc[r][0].y, acc[r][1].x, acc[r][1].y);
        *(float4 *)(dst + 4) = make_float4(acc[r][2].x, acc[r][2].y, acc[r][3].x, acc[r][3].y);
    }
}

__device__ __forceinline__ void update_phase(bool enc, int t, const float *__restrict__ bias,
                                             float *hist)
{
    int gtid = blockIdx.x * 256 + threadIdx.x;
#pragma unroll
    for (int it = 0; it < 2; ++it) {
        int id = gtid + it * NBLK * 256;           // 2*32768 = 65536 exact
        int b = id >> 9, d = id & 511;
        float4 g = enc ? __ldcg((const float4 *)&g_xg[((size_t)t * BB + b) * NG + 4 * d])
                       : make_float4(0.f, 0.f, 0.f, 0.f);
#pragma unroll
        for (int sp = 0; sp < 8; ++sp) {
            const float4 v = __ldcg((const float4 *)&g_part[((size_t)sp * BB + b) * NG + 4 * d]);
            g.x += v.x; g.y += v.y; g.z += v.z; g.w += v.w;
        }
        const float4 bb = *(const float4 *)&bias[4 * d];
        float gi = g.x + bb.x, gf = g.y + bb.y, gg = g.z + bb.z, go = g.w + bb.w;
        float c  = g_c[id];
        float cn = sigm(gf) * c + sigm(gi) * tanhf(gg);
        float hn = sigm(go) * tanhf(cn);
        g_c[id] = cn;
        g_h[id] = hn;
        if (hist) hist[id] = hn;
    }
}

__global__ __launch_bounds__(256, 1) void lstm_persistent()
{
    __shared__ float Us[2][8 * 132];
    __shared__ float Ws[2][8 * 128];
    const int tid = threadIdx.x, bx = blockIdx.x;
    const int z = bx >> 4, nbase = (bx & 15) * 128;
    Slots s; make_slots(s, tid);

    for (int t = 0; t < SEQ; ++t) {
        gemm_rec(g_WE, Us, Ws, z, nbase, s, tid);
        grid_sync();
        update_phase(true, t, g_bias, (t == SEQ - 1) ? g_hist : nullptr);
        grid_sync();
    }
    for (int t = 0; t < PRED - 1; ++t) {
        gemm_rec(g_WD, Us, Ws, z, nbase, s, tid);
        grid_sync();
        update_phase(false, 0, g_biasd, g_hist + (size_t)(t + 1) * BB * DD);
        grid_sync();
    }
}

// ==================== batched output projection ====================
__global__ __launch_bounds__(256) void final_pred(const float *__restrict__ bp,
                                                  float *__restrict__ out)
{
    __shared__ float As[2][8 * 132];
    __shared__ float Bs[2][8 * 128];
    const int t = blockIdx.y, ebase = blockIdx.x * 128, tid = threadIdx.x;
    const int tm8 = (tid >> 4) * 8, tn8 = (tid & 15) * 8;
    const float *A = g_hist + (size_t)t * BB * DD;

    Slots s; make_slots(s, tid);
    float2 acc[8][4];
#pragma unroll
    for (int r = 0; r < 8; ++r)
#pragma unroll
        for (int c = 0; c < 4; ++c) acc[r][c] = make_float2(0.f, 0.f);

    float ar[4], br[4];
    auto load = [&](int kb) {
#pragma unroll
        for (int p = 0; p < 4; ++p) {
            ar[p] = A[(size_t)s.mmp[p] * DD + kb + s.klp[p]];
            br[p] = g_WpT2[(size_t)(kb + s.kwp[p]) * EPAD + ebase + s.nlp[p]];
        }
    };

    int buf = 0;
    load(0);
    stage(s, ar, br, As[0], Bs[0]);
    __syncthreads();
#pragma unroll 1
    for (int c8 = 0; c8 < 64; ++c8) {
        if (c8 < 63) load((c8 + 1) * 8);
        mma8(acc, As[buf], Bs[buf], tm8, tn8);
        if (c8 < 63) { stage(s, ar, br, As[buf ^ 1], Bs[buf ^ 1]); __syncthreads(); buf ^= 1; }
    }
#pragma unroll
    for (int r = 0; r < 8; ++r) {
        int b = tm8 + r;
        float *orow = out + ((size_t)b * PRED + t) * ENC;
        float vals[8] = {acc[r][0].x, acc[r][0].y, acc[r][1].x, acc[r][1].y,
                         acc[r][2].x, acc[r][2].y, acc[r][3].x, acc[r][3].y};
#pragma unroll
        for (int c = 0; c < 8; ++c) {
            int e = ebase + tn8 + c;
            if (e < ENC) orow[e] = vals[c] + bp[e];
        }
    }
}

extern "C" void kernel_launch(void *const *d_in, const int *in_sizes, int n_in,
                              void *d_out, int out_size)
{
    const float *x   = (const float *)d_in[0];
    const float *Wih = (const float *)d_in[1];
    const float *Whh = (const float *)d_in[2];
    const float *bih = (const float *)d_in[3];
    const float *bhh = (const float *)d_in[4];
    const float *Wp  = (const float *)d_in[5];
    const float *bp  = (const float *)d_in[6];
    float *out = (float *)d_out;

    prepA<<<4096, 256>>>(Wih, Whh, bih, bhh, Wp);
    prepB<<<NG, 128>>>(Wih, Whh, bp);
    xg_proj<<<dim3(16, SEQ), 256>>>(x);
    lstm_persistent<<<NBLK, 256>>>();
    final_pred<<<dim3(3, PRED), 256>>>(bp, out);
}